// round 15
// baseline (speedup 1.0000x reference)
#include <cuda_runtime.h>
#include <cuda_fp16.h>
#include <cstdint>

#define NMAX   100000
#define EMAX   1600000
#define DIN    128
#define DH     128
#define DOUT   16

// ---------------- device scratch --------------------------------------------
__device__ __align__(16) float g_deg[NMAX];                 // dinv = rsqrt(deg+1)
__device__ __align__(16) uint2 g_h1h[(size_t)NMAX * 32];    // x @ W1 (half2 pairs)
__device__ __align__(16) float g_h2[(size_t)NMAX * DOUT];   // relu(...) @ W2 fp32
__device__ __align__(16) uint4 g_h2hx[(size_t)NMAX * 2];    // same, 16 halves/row
__device__ __align__(16) int2 g_csr2[EMAX];                 // {src, bits(dinv[src])}
__device__ int g_cnt[NMAX];
__device__ int g_row[NMAX];
__device__ int g_cur[NMAX];
__device__ int g_excl[NMAX];
__device__ int g_bsum[128];
__device__ int g_is64;

// ---------------- helpers ---------------------------------------------------
__device__ __forceinline__ int load_idx(const void* __restrict__ ei, long long i) {
    if (g_is64) return (int)__ldg(((const long long*)ei) + i);
    return __ldg(((const int*)ei) + i);
}
__device__ __forceinline__ void ffma2(unsigned long long& d,
                                      unsigned long long a, unsigned long long b) {
    asm("fma.rn.f32x2 %0, %1, %2, %0;" : "+l"(d) : "l"(a), "l"(b));
}
__device__ __forceinline__ unsigned long long pack2(float lo, float hi) {
    unsigned long long r;
    asm("mov.b64 %0, {%1, %2};" : "=l"(r) : "f"(lo), "f"(hi));
    return r;
}
__device__ __forceinline__ float2 unpack2(unsigned long long v) {
    float lo, hi;
    asm("mov.b64 {%0, %1}, %2;" : "=f"(lo), "=f"(hi) : "l"(v));
    return make_float2(lo, hi);
}
__device__ __forceinline__ float2 h2f2(uint32_t u) {
    return __half22float2(*reinterpret_cast<__half2*>(&u));
}

// ---------------- CSR construction ------------------------------------------
__global__ void k_init(const void* __restrict__ ei, int n) {
    int i = blockIdx.x * blockDim.x + threadIdx.x;
    if (i < n) g_cnt[i] = 0;
    if (i == 0) {
        const unsigned long long* p = (const unsigned long long*)ei;
        int is64 = 1;
        for (int k = 0; k < 64; k++)
            if ((p[k] >> 32) != 0ull) { is64 = 0; break; }
        g_is64 = is64;
    }
}

__global__ void k_count(const void* __restrict__ ei, int e) {
    int i = blockIdx.x * blockDim.x + threadIdx.x;
    if (i < e) atomicAdd(&g_cnt[load_idx(ei, (long long)e + i)], 1);
}

__global__ void k_scan1(int n) {
    __shared__ int sh[256];
    int t = threadIdx.x;
    int base = blockIdx.x * 1024;
    int v[4], s = 0;
#pragma unroll
    for (int i = 0; i < 4; i++) {
        int idx = base + t * 4 + i;
        v[i] = (idx < n) ? g_cnt[idx] : 0;
        s += v[i];
    }
    sh[t] = s;
    __syncthreads();
    int own = s;
    for (int off = 1; off < 256; off <<= 1) {
        int o = (t >= off) ? sh[t - off] : 0;
        __syncthreads();
        sh[t] += o;
        __syncthreads();
    }
    if (t == 255) g_bsum[blockIdx.x] = sh[255];
    int run = sh[t] - own;
#pragma unroll
    for (int i = 0; i < 4; i++) {
        int idx = base + t * 4 + i;
        if (idx < n) g_excl[idx] = run;
        run += v[i];
    }
}

// scan3 (merged with scan2): block b covers nodes [b*1024, b*1024+1024);
// warp 0 reduces bsum[0..b-1] -> block prefix; then finalize row/cur/deg.
__global__ void k_scan3(int n) {
    __shared__ int s_pre;
    int t = threadIdx.x;
    int b = blockIdx.x;
    if (t < 32) {
        int s = 0;
        for (int j = t; j < b; j += 32) s += g_bsum[j];
#pragma unroll
        for (int m = 16; m >= 1; m >>= 1) s += __shfl_xor_sync(0xffffffffu, s, m);
        if (t == 0) s_pre = s;
    }
    __syncthreads();
    int pre = s_pre;
#pragma unroll
    for (int q = 0; q < 4; q++) {
        int i = b * 1024 + q * 256 + t;
        if (i < n) {
            int r = g_excl[i] + pre;
            g_row[i] = r;
            g_cur[i] = r;
            g_deg[i] = rsqrtf((float)g_cnt[i] + 1.0f);
        }
    }
}

// fill CSR with {src, dinv[src]} pairs (dinv available: scan3 done)
__global__ void k_fill(const void* __restrict__ ei, int e) {
    int i = blockIdx.x * blockDim.x + threadIdx.x;
    if (i < e) {
        int s = load_idx(ei, i);
        int d = load_idx(ei, (long long)e + i);
        int pos = atomicAdd(&g_cur[d], 1);
        int2 c;
        c.x = s;
        c.y = __float_as_int(__ldg(&g_deg[s]));
        g_csr2[pos] = c;
    }
}

// ---------------- GEMM1: h1h = fp16(x @ W1)  (FFMA2, transposed X tile) -----
#define GTM 64
#define XTS 66
__global__ void k_gemm1(const float* __restrict__ x,
                        const float* __restrict__ W1, int n) {
    extern __shared__ float sm[];
    float* Ws = sm;                 // 128*128
    float* Xt = sm + DIN * DH;      // [DIN][XTS]
    int t = threadIdx.x;

    for (int i = t; i < DIN * DH / 4; i += 256)
        reinterpret_cast<float4*>(Ws)[i] = reinterpret_cast<const float4*>(W1)[i];

    int row0 = blockIdx.x * GTM;
    for (int i = t; i < GTM * 32; i += 256) {
        int r = i >> 5, c4 = i & 31;
        int gr = row0 + r;
        float4 v = make_float4(0.f, 0.f, 0.f, 0.f);
        if (gr < n) v = reinterpret_cast<const float4*>(x)[(size_t)gr * 32 + c4];
        Xt[(c4 * 4 + 0) * XTS + r] = v.x;
        Xt[(c4 * 4 + 1) * XTS + r] = v.y;
        Xt[(c4 * 4 + 2) * XTS + r] = v.z;
        Xt[(c4 * 4 + 3) * XTS + r] = v.w;
    }
    __syncthreads();

    int cx = t & 31;
    int ry = t >> 5;
    unsigned long long acc[4][4];
#pragma unroll
    for (int p = 0; p < 4; p++)
#pragma unroll
        for (int c = 0; c < 4; c++) acc[p][c] = 0ull;

#pragma unroll 4
    for (int k = 0; k < DIN; k++) {
        float4 w = reinterpret_cast<const float4*>(Ws)[k * 32 + cx];
        unsigned long long ws[4];
        ws[0] = pack2(w.x, w.x); ws[1] = pack2(w.y, w.y);
        ws[2] = pack2(w.z, w.z); ws[3] = pack2(w.w, w.w);
        const unsigned long long* arow =
            reinterpret_cast<const unsigned long long*>(&Xt[k * XTS + ry * 8]);
#pragma unroll
        for (int p = 0; p < 4; p++) {
            unsigned long long ap = arow[p];
            ffma2(acc[p][0], ap, ws[0]);
            ffma2(acc[p][1], ap, ws[1]);
            ffma2(acc[p][2], ap, ws[2]);
            ffma2(acc[p][3], ap, ws[3]);
        }
    }
#pragma unroll
    for (int p = 0; p < 4; p++) {
        int gr = row0 + ry * 8 + 2 * p;
        float2 c0 = unpack2(acc[p][0]);
        float2 c1 = unpack2(acc[p][1]);
        float2 c2 = unpack2(acc[p][2]);
        float2 c3 = unpack2(acc[p][3]);
        if (gr < n) {
            __half2 h0 = __floats2half2_rn(c0.x, c1.x);
            __half2 h1 = __floats2half2_rn(c2.x, c3.x);
            uint2 u;
            u.x = *reinterpret_cast<uint32_t*>(&h0);
            u.y = *reinterpret_cast<uint32_t*>(&h1);
            g_h1h[(size_t)gr * 32 + cx] = u;
        }
        if (gr + 1 < n) {
            __half2 h0 = __floats2half2_rn(c0.y, c1.y);
            __half2 h1 = __floats2half2_rn(c2.y, c3.y);
            uint2 u;
            u.x = *reinterpret_cast<uint32_t*>(&h0);
            u.y = *reinterpret_cast<uint32_t*>(&h1);
            g_h1h[(size_t)(gr + 1) * 32 + cx] = u;
        }
    }
}

// ---------------- fused layer 1: gather + relu + GEMM2 ----------------------
// Phase 1: warp-per-node gather (weight embedded in CSR entry) -> smem row.
// Phase 2: all 512 threads split the 128x16 GEMV (k-halves), combine in smem.
__global__ void __launch_bounds__(512) k_layer1(const float* __restrict__ b1,
                                                const float* __restrict__ W2, int n) {
    __shared__ float W2s[DH * DOUT];
    __shared__ float b1s[DH];
    __shared__ float vbuf[16 * 132];
    __shared__ float pbuf[256];
    int t = threadIdx.x;
    for (int i = t; i < DH * DOUT; i += 512) W2s[i] = W2[i];
    if (t < DH) b1s[t] = b1[t];
    __syncthreads();

    int warp = t >> 5, lane = t & 31;
    int node = blockIdx.x * 16 + warp;
    if (node < n) {
        int beg = g_row[node];
        int end = beg + g_cnt[node];
        float4 acc = make_float4(0.f, 0.f, 0.f, 0.f);
        int p = beg;
        for (; p + 3 < end; p += 4) {
            int2 c0 = g_csr2[p],     c1 = g_csr2[p + 1];
            int2 c2 = g_csr2[p + 2], c3 = g_csr2[p + 3];
            float w0 = __int_as_float(c0.y), w1 = __int_as_float(c1.y);
            float w2 = __int_as_float(c2.y), w3 = __int_as_float(c3.y);
            uint2 u0 = g_h1h[(size_t)c0.x * 32 + lane];
            uint2 u1 = g_h1h[(size_t)c1.x * 32 + lane];
            uint2 u2 = g_h1h[(size_t)c2.x * 32 + lane];
            uint2 u3 = g_h1h[(size_t)c3.x * 32 + lane];
            float2 a0 = h2f2(u0.x), b0 = h2f2(u0.y);
            float2 a1 = h2f2(u1.x), b1v = h2f2(u1.y);
            float2 a2 = h2f2(u2.x), b2v = h2f2(u2.y);
            float2 a3 = h2f2(u3.x), b3v = h2f2(u3.y);
            acc.x += a0.x * w0 + a1.x * w1 + a2.x * w2 + a3.x * w3;
            acc.y += a0.y * w0 + a1.y * w1 + a2.y * w2 + a3.y * w3;
            acc.z += b0.x * w0 + b1v.x * w1 + b2v.x * w2 + b3v.x * w3;
            acc.w += b0.y * w0 + b1v.y * w1 + b2v.y * w2 + b3v.y * w3;
        }
        for (; p < end; p++) {
            int2 c0 = g_csr2[p];
            float w0 = __int_as_float(c0.y);
            uint2 u0 = g_h1h[(size_t)c0.x * 32 + lane];
            float2 a0 = h2f2(u0.x), b0 = h2f2(u0.y);
            acc.x = fmaf(a0.x, w0, acc.x);
            acc.y = fmaf(a0.y, w0, acc.y);
            acc.z = fmaf(b0.x, w0, acc.z);
            acc.w = fmaf(b0.y, w0, acc.w);
        }
        float di = g_deg[node];
        float dd = di * di;
        uint2 us = g_h1h[(size_t)node * 32 + lane];
        float2 s0 = h2f2(us.x), s1 = h2f2(us.y);
        float4 bb = *reinterpret_cast<const float4*>(&b1s[lane * 4]);
        float4 v;
        v.x = fmaxf(fmaf(acc.x, di, fmaf(s0.x, dd, bb.x)), 0.f);
        v.y = fmaxf(fmaf(acc.y, di, fmaf(s0.y, dd, bb.y)), 0.f);
        v.z = fmaxf(fmaf(acc.z, di, fmaf(s1.x, dd, bb.z)), 0.f);
        v.w = fmaxf(fmaf(acc.w, di, fmaf(s1.y, dd, bb.w)), 0.f);
        *reinterpret_cast<float4*>(&vbuf[warp * 132 + lane * 4]) = v;
    }
    __syncthreads();

    // Phase 2: thread t<256 does k=0..63 for (nl,j); t>=256 does k=64..127.
    {
        int tt = t & 255;
        int nl = tt >> 4;
        int j = tt & 15;
        int node2 = blockIdx.x * 16 + nl;
        int k0 = (t >= 256) ? 64 : 0;
        float acc = 0.f;
        if (node2 < n) {
            const float* vr = &vbuf[nl * 132 + k0];
            const float* wr = &W2s[k0 * DOUT + j];
#pragma unroll 8
            for (int k = 0; k < 64; k++)
                acc = fmaf(vr[k], wr[k * DOUT], acc);
        }
        if (t >= 256) pbuf[tt] = acc;
        __syncthreads();
        if (t < 256 && node2 < n) {
            acc += pbuf[tt];
            g_h2[(size_t)node2 * DOUT + j] = acc;
            float nb = __shfl_xor_sync(0xffffffffu, acc, 1);
            if ((j & 1) == 0) {
                __half2 hp = __floats2half2_rn(acc, nb);
                ((uint32_t*)g_h2hx)[(size_t)node2 * 8 + (j >> 1)] =
                    *reinterpret_cast<uint32_t*>(&hp);
            }
        }
    }
}

// ---------------- layer-2 aggregation (fp16 gather, weight in CSR) ----------
__global__ void k_agg2(float* __restrict__ out, const float* __restrict__ b2, int n) {
    long long tid = (long long)blockIdx.x * blockDim.x + threadIdx.x;
    int node = (int)(tid >> 5);
    int lane = threadIdx.x & 31;
    if (node >= n) return;
    int eg = lane >> 1;
    int ch = lane & 1;
    int beg = g_row[node];
    int end = beg + g_cnt[node];
    float4 acc = make_float4(0.f, 0.f, 0.f, 0.f);
    float4 acc2 = make_float4(0.f, 0.f, 0.f, 0.f);
    for (int p0 = beg; p0 < end; p0 += 16) {
        int p = p0 + eg;
        if (p < end) {
            int2 c = g_csr2[p];
            float w = __int_as_float(c.y);
            uint4 u = g_h2hx[(size_t)c.x * 2 + ch];
            float2 f0 = h2f2(u.x), f1 = h2f2(u.y), f2 = h2f2(u.z), f3 = h2f2(u.w);
            acc.x  = fmaf(f0.x, w, acc.x);
            acc.y  = fmaf(f0.y, w, acc.y);
            acc.z  = fmaf(f1.x, w, acc.z);
            acc.w  = fmaf(f1.y, w, acc.w);
            acc2.x = fmaf(f2.x, w, acc2.x);
            acc2.y = fmaf(f2.y, w, acc2.y);
            acc2.z = fmaf(f3.x, w, acc2.z);
            acc2.w = fmaf(f3.y, w, acc2.w);
        }
    }
#pragma unroll
    for (int m = 2; m <= 16; m <<= 1) {
        acc.x  += __shfl_xor_sync(0xffffffffu, acc.x,  m);
        acc.y  += __shfl_xor_sync(0xffffffffu, acc.y,  m);
        acc.z  += __shfl_xor_sync(0xffffffffu, acc.z,  m);
        acc.w  += __shfl_xor_sync(0xffffffffu, acc.w,  m);
        acc2.x += __shfl_xor_sync(0xffffffffu, acc2.x, m);
        acc2.y += __shfl_xor_sync(0xffffffffu, acc2.y, m);
        acc2.z += __shfl_xor_sync(0xffffffffu, acc2.z, m);
        acc2.w += __shfl_xor_sync(0xffffffffu, acc2.w, m);
    }
    if (lane < 2) {
        float di = g_deg[node];
        float dd = di * di;
        int c0 = lane * 2;
        float4 bb0 = reinterpret_cast<const float4*>(b2)[c0];
        float4 bb1 = reinterpret_cast<const float4*>(b2)[c0 + 1];
        float4 hv0 = reinterpret_cast<const float4*>(g_h2)[(size_t)node * 4 + c0];
        float4 hv1 = reinterpret_cast<const float4*>(g_h2)[(size_t)node * 4 + c0 + 1];
        float4 o0, o1;
        o0.x = bb0.x + fmaf(hv0.x, dd, acc.x  * di);
        o0.y = bb0.y + fmaf(hv0.y, dd, acc.y  * di);
        o0.z = bb0.z + fmaf(hv0.z, dd, acc.z  * di);
        o0.w = bb0.w + fmaf(hv0.w, dd, acc.w  * di);
        o1.x = bb1.x + fmaf(hv1.x, dd, acc2.x * di);
        o1.y = bb1.y + fmaf(hv1.y, dd, acc2.y * di);
        o1.z = bb1.z + fmaf(hv1.z, dd, acc2.z * di);
        o1.w = bb1.w + fmaf(hv1.w, dd, acc2.w * di);
        reinterpret_cast<float4*>(out)[(size_t)node * 4 + c0]     = o0;
        reinterpret_cast<float4*>(out)[(size_t)node * 4 + c0 + 1] = o1;
    }
}

// ---------------- launch -----------------------------------------------------
extern "C" void kernel_launch(void* const* d_in, const int* in_sizes, int n_in,
                              void* d_out, int out_size) {
    const float* x  = (const float*)d_in[0];
    const void*  ei = d_in[1];
    const float* W1 = (const float*)d_in[2];
    const float* b1 = (const float*)d_in[3];
    const float* W2 = (const float*)d_in[4];
    const float* b2 = (const float*)d_in[5];
    float* out = (float*)d_out;

    int n = in_sizes[0] / DIN;
    int e = in_sizes[1] / 2;

    static cudaStream_t s2 = 0;
    static cudaEvent_t evA = 0, evB = 0;
    static int tried = 0;
    if (!tried) {
        tried = 1;
        if (cudaStreamCreateWithFlags(&s2, cudaStreamNonBlocking) != cudaSuccess) s2 = 0;
        if (s2) {
            if (cudaEventCreateWithFlags(&evA, cudaEventDisableTiming) != cudaSuccess ||
                cudaEventCreateWithFlags(&evB, cudaEventDisableTiming) != cudaSuccess) {
                s2 = 0;
            }
        }
    }
    cudaStream_t sc = s2 ? s2 : 0;

    if (s2) {
        cudaEventRecord(evA, 0);
        cudaStreamWaitEvent(s2, evA, 0);
    }

    // CSR build (side stream) — independent of gemm1
    k_init<<<(n + 255) / 256, 256, 0, sc>>>(ei, n);
    k_count<<<(e + 255) / 256, 256, 0, sc>>>(ei, e);
    int nb = (n + 1023) / 1024;
    k_scan1<<<nb, 256, 0, sc>>>(n);
    k_scan3<<<nb, 256, 0, sc>>>(n);
    k_fill<<<(e + 255) / 256, 256, 0, sc>>>(ei, e);

    // GEMM1 (default stream, concurrent with CSR build)
    int smem = (DIN * DH + DIN * XTS) * (int)sizeof(float);   // ~97 KB
    cudaFuncSetAttribute(k_gemm1, cudaFuncAttributeMaxDynamicSharedMemorySize, smem);
    k_gemm1<<<(n + GTM - 1) / GTM, 256, smem>>>(x, W1, n);

    if (s2) {
        cudaEventRecord(evB, s2);
        cudaStreamWaitEvent(0, evB, 0);
    }

    k_layer1<<<(n + 15) / 16, 512>>>(b1, W2, n);
    long long thr = (long long)n * 32;
    k_agg2<<<(unsigned)((thr + 255) / 256), 256>>>(out, b2, n);
}

// round 16
// speedup vs baseline: 1.0024x; 1.0024x over previous
#include <cuda_runtime.h>
#include <cuda_fp16.h>
#include <cstdint>

#define NMAX   100000
#define EMAX   1600000
#define DIN    128
#define DH     128
#define DOUT   16

// ---------------- device scratch --------------------------------------------
__device__ __align__(16) float g_deg[NMAX];                 // dinv = rsqrt(deg+1)
__device__ __align__(16) uint2 g_h1h[(size_t)NMAX * 32];    // x @ W1 (half2 pairs)
__device__ __align__(16) float g_h2[(size_t)NMAX * DOUT];   // relu(...) @ W2 fp32
__device__ __align__(16) uint4 g_h2hx[(size_t)NMAX * 2];    // same, 16 halves/row
__device__ int g_csr[EMAX];                                 // src indices by dst
__device__ int g_cnt[NMAX];   // zero at load; k_agg2 re-zeroes each call
__device__ int g_row[NMAX];
__device__ int g_cur[NMAX];
__device__ int g_excl[NMAX];
__device__ int g_bsum[128];

// ---------------- helpers ---------------------------------------------------
__device__ __forceinline__ void ffma2(unsigned long long& d,
                                      unsigned long long a, unsigned long long b) {
    asm("fma.rn.f32x2 %0, %1, %2, %0;" : "+l"(d) : "l"(a), "l"(b));
}
__device__ __forceinline__ unsigned long long pack2(float lo, float hi) {
    unsigned long long r;
    asm("mov.b64 %0, {%1, %2};" : "=l"(r) : "f"(lo), "f"(hi));
    return r;
}
__device__ __forceinline__ float2 unpack2(unsigned long long v) {
    float lo, hi;
    asm("mov.b64 {%0, %1}, %2;" : "=f"(lo), "=f"(hi) : "l"(v));
    return make_float2(lo, hi);
}
__device__ __forceinline__ float2 h2f2(uint32_t u) {
    return __half22float2(*reinterpret_cast<__half2*>(&u));
}
// per-block edge-index dtype detect: warp 0 ballots high words of first 32
// qwords (true int64 edge data has all-zero high words; packed int32 aliases
// random indices there — misdetect prob (1e-5)^32).
#define DETECT_IS64(ei, s64)                                                 \
    do {                                                                     \
        if (threadIdx.x < 32) {                                              \
            const unsigned long long* _p = (const unsigned long long*)(ei);  \
            unsigned long long _v = _p[threadIdx.x];                         \
            unsigned _m = __ballot_sync(0xffffffffu, (_v >> 32) != 0ull);    \
            if (threadIdx.x == 0) (s64) = (_m == 0u);                        \
        }                                                                    \
        __syncthreads();                                                     \
    } while (0)

// ---------------- CSR construction ------------------------------------------
__global__ void k_count(const void* __restrict__ ei, int e) {
    __shared__ int s64;
    DETECT_IS64(ei, s64);
    int is64 = s64;
    int i = blockIdx.x * blockDim.x + threadIdx.x;
    if (i < e) {
        int d = is64 ? (int)__ldg(((const long long*)ei) + e + i)
                     : __ldg(((const int*)ei) + e + i);
        atomicAdd(&g_cnt[d], 1);
    }
}

__global__ void k_scan1(int n) {
    __shared__ int sh[256];
    int t = threadIdx.x;
    int base = blockIdx.x * 1024;
    int v[4], s = 0;
#pragma unroll
    for (int i = 0; i < 4; i++) {
        int idx = base + t * 4 + i;
        v[i] = (idx < n) ? g_cnt[idx] : 0;
        s += v[i];
    }
    sh[t] = s;
    __syncthreads();
    int own = s;
    for (int off = 1; off < 256; off <<= 1) {
        int o = (t >= off) ? sh[t - off] : 0;
        __syncthreads();
        sh[t] += o;
        __syncthreads();
    }
    if (t == 255) g_bsum[blockIdx.x] = sh[255];
    int run = sh[t] - own;
#pragma unroll
    for (int i = 0; i < 4; i++) {
        int idx = base + t * 4 + i;
        if (idx < n) g_excl[idx] = run;
        run += v[i];
    }
}

// scan3 (merged scan2): block b reduces bsum[0..b-1] -> prefix, finalizes.
__global__ void k_scan3(int n) {
    __shared__ int s_pre;
    int t = threadIdx.x;
    int b = blockIdx.x;
    if (t < 32) {
        int s = 0;
        for (int j = t; j < b; j += 32) s += g_bsum[j];
#pragma unroll
        for (int m = 16; m >= 1; m >>= 1) s += __shfl_xor_sync(0xffffffffu, s, m);
        if (t == 0) s_pre = s;
    }
    __syncthreads();
    int pre = s_pre;
#pragma unroll
    for (int q = 0; q < 4; q++) {
        int i = b * 1024 + q * 256 + t;
        if (i < n) {
            int r = g_excl[i] + pre;
            g_row[i] = r;
            g_cur[i] = r;
            g_deg[i] = rsqrtf((float)g_cnt[i] + 1.0f);
        }
    }
}

__global__ void k_fill(const void* __restrict__ ei, int e) {
    __shared__ int s64;
    DETECT_IS64(ei, s64);
    int is64 = s64;
    int i = blockIdx.x * blockDim.x + threadIdx.x;
    if (i < e) {
        int s, d;
        if (is64) {
            s = (int)__ldg(((const long long*)ei) + i);
            d = (int)__ldg(((const long long*)ei) + e + i);
        } else {
            s = __ldg(((const int*)ei) + i);
            d = __ldg(((const int*)ei) + e + i);
        }
        int pos = atomicAdd(&g_cur[d], 1);
        g_csr[pos] = s;
    }
}

// ---------------- GEMM1: h1h = fp16(x @ W1)  (FFMA2, transposed X tile) -----
#define GTM 64
#define XTS 66
__global__ void k_gemm1(const float* __restrict__ x,
                        const float* __restrict__ W1, int n) {
    extern __shared__ float sm[];
    float* Ws = sm;                 // 128*128
    float* Xt = sm + DIN * DH;      // [DIN][XTS]
    int t = threadIdx.x;

    for (int i = t; i < DIN * DH / 4; i += 256)
        reinterpret_cast<float4*>(Ws)[i] = reinterpret_cast<const float4*>(W1)[i];

    int row0 = blockIdx.x * GTM;
    for (int i = t; i < GTM * 32; i += 256) {
        int r = i >> 5, c4 = i & 31;
        int gr = row0 + r;
        float4 v = make_float4(0.f, 0.f, 0.f, 0.f);
        if (gr < n) v = reinterpret_cast<const float4*>(x)[(size_t)gr * 32 + c4];
        Xt[(c4 * 4 + 0) * XTS + r] = v.x;
        Xt[(c4 * 4 + 1) * XTS + r] = v.y;
        Xt[(c4 * 4 + 2) * XTS + r] = v.z;
        Xt[(c4 * 4 + 3) * XTS + r] = v.w;
    }
    __syncthreads();

    int cx = t & 31;
    int ry = t >> 5;
    unsigned long long acc[4][4];
#pragma unroll
    for (int p = 0; p < 4; p++)
#pragma unroll
        for (int c = 0; c < 4; c++) acc[p][c] = 0ull;

#pragma unroll 4
    for (int k = 0; k < DIN; k++) {
        float4 w = reinterpret_cast<const float4*>(Ws)[k * 32 + cx];
        unsigned long long ws[4];
        ws[0] = pack2(w.x, w.x); ws[1] = pack2(w.y, w.y);
        ws[2] = pack2(w.z, w.z); ws[3] = pack2(w.w, w.w);
        const unsigned long long* arow =
            reinterpret_cast<const unsigned long long*>(&Xt[k * XTS + ry * 8]);
#pragma unroll
        for (int p = 0; p < 4; p++) {
            unsigned long long ap = arow[p];
            ffma2(acc[p][0], ap, ws[0]);
            ffma2(acc[p][1], ap, ws[1]);
            ffma2(acc[p][2], ap, ws[2]);
            ffma2(acc[p][3], ap, ws[3]);
        }
    }
#pragma unroll
    for (int p = 0; p < 4; p++) {
        int gr = row0 + ry * 8 + 2 * p;
        float2 c0 = unpack2(acc[p][0]);
        float2 c1 = unpack2(acc[p][1]);
        float2 c2 = unpack2(acc[p][2]);
        float2 c3 = unpack2(acc[p][3]);
        if (gr < n) {
            __half2 h0 = __floats2half2_rn(c0.x, c1.x);
            __half2 h1 = __floats2half2_rn(c2.x, c3.x);
            uint2 u;
            u.x = *reinterpret_cast<uint32_t*>(&h0);
            u.y = *reinterpret_cast<uint32_t*>(&h1);
            g_h1h[(size_t)gr * 32 + cx] = u;
        }
        if (gr + 1 < n) {
            __half2 h0 = __floats2half2_rn(c0.y, c1.y);
            __half2 h1 = __floats2half2_rn(c2.y, c3.y);
            uint2 u;
            u.x = *reinterpret_cast<uint32_t*>(&h0);
            u.y = *reinterpret_cast<uint32_t*>(&h1);
            g_h1h[(size_t)(gr + 1) * 32 + cx] = u;
        }
    }
}

// ---------------- fused layer 1: gather + relu + GEMM2 ----------------------
__global__ void __launch_bounds__(512) k_layer1(const float* __restrict__ b1,
                                                const float* __restrict__ W2, int n) {
    __shared__ float W2s[DH * DOUT];
    __shared__ float b1s[DH];
    __shared__ float vbuf[16 * 132];
    __shared__ float pbuf[256];
    int t = threadIdx.x;
    for (int i = t; i < DH * DOUT; i += 512) W2s[i] = W2[i];
    if (t < DH) b1s[t] = b1[t];
    __syncthreads();

    int warp = t >> 5, lane = t & 31;
    int node = blockIdx.x * 16 + warp;
    if (node < n) {
        int beg = g_row[node];
        int end = beg + g_cnt[node];
        float4 acc = make_float4(0.f, 0.f, 0.f, 0.f);
        int p = beg;
        for (; p + 3 < end; p += 4) {
            int s0 = __ldg(&g_csr[p]),     s1 = __ldg(&g_csr[p + 1]);
            int s2 = __ldg(&g_csr[p + 2]), s3 = __ldg(&g_csr[p + 3]);
            float w0 = g_deg[s0], w1 = g_deg[s1], w2 = g_deg[s2], w3 = g_deg[s3];
            uint2 u0 = g_h1h[(size_t)s0 * 32 + lane];
            uint2 u1 = g_h1h[(size_t)s1 * 32 + lane];
            uint2 u2 = g_h1h[(size_t)s2 * 32 + lane];
            uint2 u3 = g_h1h[(size_t)s3 * 32 + lane];
            float2 a0 = h2f2(u0.x), b0 = h2f2(u0.y);
            float2 a1 = h2f2(u1.x), b1v = h2f2(u1.y);
            float2 a2 = h2f2(u2.x), b2v = h2f2(u2.y);
            float2 a3 = h2f2(u3.x), b3v = h2f2(u3.y);
            acc.x += a0.x * w0 + a1.x * w1 + a2.x * w2 + a3.x * w3;
            acc.y += a0.y * w0 + a1.y * w1 + a2.y * w2 + a3.y * w3;
            acc.z += b0.x * w0 + b1v.x * w1 + b2v.x * w2 + b3v.x * w3;
            acc.w += b0.y * w0 + b1v.y * w1 + b2v.y * w2 + b3v.y * w3;
        }
        for (; p < end; p++) {
            int s0 = __ldg(&g_csr[p]);
            float w0 = g_deg[s0];
            uint2 u0 = g_h1h[(size_t)s0 * 32 + lane];
            float2 a0 = h2f2(u0.x), b0 = h2f2(u0.y);
            acc.x = fmaf(a0.x, w0, acc.x);
            acc.y = fmaf(a0.y, w0, acc.y);
            acc.z = fmaf(b0.x, w0, acc.z);
            acc.w = fmaf(b0.y, w0, acc.w);
        }
        float di = g_deg[node];
        float dd = di * di;
        uint2 us = g_h1h[(size_t)node * 32 + lane];
        float2 s0 = h2f2(us.x), s1 = h2f2(us.y);
        float4 bb = *reinterpret_cast<const float4*>(&b1s[lane * 4]);
        float4 v;
        v.x = fmaxf(fmaf(acc.x, di, fmaf(s0.x, dd, bb.x)), 0.f);
        v.y = fmaxf(fmaf(acc.y, di, fmaf(s0.y, dd, bb.y)), 0.f);
        v.z = fmaxf(fmaf(acc.z, di, fmaf(s1.x, dd, bb.z)), 0.f);
        v.w = fmaxf(fmaf(acc.w, di, fmaf(s1.y, dd, bb.w)), 0.f);
        *reinterpret_cast<float4*>(&vbuf[warp * 132 + lane * 4]) = v;
    }
    __syncthreads();

    // Phase 2: t<256 -> k 0..63; t>=256 -> k 64..127; combine via pbuf.
    {
        int tt = t & 255;
        int nl = tt >> 4;
        int j = tt & 15;
        int node2 = blockIdx.x * 16 + nl;
        int k0 = (t >= 256) ? 64 : 0;
        float acc = 0.f;
        if (node2 < n) {
            const float* vr = &vbuf[nl * 132 + k0];
            const float* wr = &W2s[k0 * DOUT + j];
#pragma unroll 8
            for (int k = 0; k < 64; k++)
                acc = fmaf(vr[k], wr[k * DOUT], acc);
        }
        if (t >= 256) pbuf[tt] = acc;
        __syncthreads();
        if (t < 256 && node2 < n) {
            acc += pbuf[tt];
            g_h2[(size_t)node2 * DOUT + j] = acc;
            float nb = __shfl_xor_sync(0xffffffffu, acc, 1);
            if ((j & 1) == 0) {
                __half2 hp = __floats2half2_rn(acc, nb);
                ((uint32_t*)g_h2hx)[(size_t)node2 * 8 + (j >> 1)] =
                    *reinterpret_cast<uint32_t*>(&hp);
            }
        }
    }
}

// ---------------- layer-2 aggregation (fp16 gather) + cnt restore -----------
__global__ void k_agg2(float* __restrict__ out, const float* __restrict__ b2, int n) {
    long long tid = (long long)blockIdx.x * blockDim.x + threadIdx.x;
    int node = (int)(tid >> 5);
    int lane = threadIdx.x & 31;
    if (node >= n) return;
    int eg = lane >> 1;
    int ch = lane & 1;
    int beg = g_row[node];
    int end = beg + g_cnt[node];
    float4 acc = make_float4(0.f, 0.f, 0.f, 0.f);
    float4 acc2 = make_float4(0.f, 0.f, 0.f, 0.f);
    for (int p0 = beg; p0 < end; p0 += 16) {
        int p = p0 + eg;
        if (p < end) {
            int s = __ldg(&g_csr[p]);
            float w = g_deg[s];
            uint4 u = g_h2hx[(size_t)s * 2 + ch];
            float2 f0 = h2f2(u.x), f1 = h2f2(u.y), f2 = h2f2(u.z), f3 = h2f2(u.w);
            acc.x  = fmaf(f0.x, w, acc.x);
            acc.y  = fmaf(f0.y, w, acc.y);
            acc.z  = fmaf(f1.x, w, acc.z);
            acc.w  = fmaf(f1.y, w, acc.w);
            acc2.x = fmaf(f2.x, w, acc2.x);
            acc2.y = fmaf(f2.y, w, acc2.y);
            acc2.z = fmaf(f3.x, w, acc2.z);
            acc2.w = fmaf(f3.y, w, acc2.w);
        }
    }
#pragma unroll
    for (int m = 2; m <= 16; m <<= 1) {
        acc.x  += __shfl_xor_sync(0xffffffffu, acc.x,  m);
        acc.y  += __shfl_xor_sync(0xffffffffu, acc.y,  m);
        acc.z  += __shfl_xor_sync(0xffffffffu, acc.z,  m);
        acc.w  += __shfl_xor_sync(0xffffffffu, acc.w,  m);
        acc2.x += __shfl_xor_sync(0xffffffffu, acc2.x, m);
        acc2.y += __shfl_xor_sync(0xffffffffu, acc2.y, m);
        acc2.z += __shfl_xor_sync(0xffffffffu, acc2.z, m);
        acc2.w += __shfl_xor_sync(0xffffffffu, acc2.w, m);
    }
    if (lane < 2) {
        float di = g_deg[node];
        float dd = di * di;
        int c0 = lane * 2;
        float4 bb0 = reinterpret_cast<const float4*>(b2)[c0];
        float4 bb1 = reinterpret_cast<const float4*>(b2)[c0 + 1];
        float4 hv0 = reinterpret_cast<const float4*>(g_h2)[(size_t)node * 4 + c0];
        float4 hv1 = reinterpret_cast<const float4*>(g_h2)[(size_t)node * 4 + c0 + 1];
        float4 o0, o1;
        o0.x = bb0.x + fmaf(hv0.x, dd, acc.x  * di);
        o0.y = bb0.y + fmaf(hv0.y, dd, acc.y  * di);
        o0.z = bb0.z + fmaf(hv0.z, dd, acc.z  * di);
        o0.w = bb0.w + fmaf(hv0.w, dd, acc.w  * di);
        o1.x = bb1.x + fmaf(hv1.x, dd, acc2.x * di);
        o1.y = bb1.y + fmaf(hv1.y, dd, acc2.y * di);
        o1.z = bb1.z + fmaf(hv1.z, dd, acc2.z * di);
        o1.w = bb1.w + fmaf(hv1.w, dd, acc2.w * di);
        reinterpret_cast<float4*>(out)[(size_t)node * 4 + c0]     = o0;
        reinterpret_cast<float4*>(out)[(size_t)node * 4 + c0 + 1] = o1;
    }
    // restore g_cnt to zero for the next call (deterministic invariant)
    if (lane == 0) g_cnt[node] = 0;
}

// ---------------- launch -----------------------------------------------------
extern "C" void kernel_launch(void* const* d_in, const int* in_sizes, int n_in,
                              void* d_out, int out_size) {
    const float* x  = (const float*)d_in[0];
    const void*  ei = d_in[1];
    const float* W1 = (const float*)d_in[2];
    const float* b1 = (const float*)d_in[3];
    const float* W2 = (const float*)d_in[4];
    const float* b2 = (const float*)d_in[5];
    float* out = (float*)d_out;

    int n = in_sizes[0] / DIN;
    int e = in_sizes[1] / 2;

    static cudaStream_t s2 = 0;
    static cudaEvent_t evA = 0, evB = 0;
    static int tried = 0;
    if (!tried) {
        tried = 1;
        if (cudaStreamCreateWithFlags(&s2, cudaStreamNonBlocking) != cudaSuccess) s2 = 0;
        if (s2) {
            if (cudaEventCreateWithFlags(&evA, cudaEventDisableTiming) != cudaSuccess ||
                cudaEventCreateWithFlags(&evB, cudaEventDisableTiming) != cudaSuccess) {
                s2 = 0;
            }
        }
    }
    cudaStream_t sc = s2 ? s2 : 0;

    if (s2) {
        cudaEventRecord(evA, 0);
        cudaStreamWaitEvent(s2, evA, 0);
    }

    // CSR build (side stream) — g_cnt arrives zeroed (BSS init / k_agg2 restore)
    k_count<<<(e + 255) / 256, 256, 0, sc>>>(ei, e);
    int nb = (n + 1023) / 1024;
    k_scan1<<<nb, 256, 0, sc>>>(n);
    k_scan3<<<nb, 256, 0, sc>>>(n);
    k_fill<<<(e + 255) / 256, 256, 0, sc>>>(ei, e);

    // GEMM1 (default stream, concurrent with CSR build)
    int smem = (DIN * DH + DIN * XTS) * (int)sizeof(float);   // ~97 KB
    cudaFuncSetAttribute(k_gemm1, cudaFuncAttributeMaxDynamicSharedMemorySize, smem);
    k_gemm1<<<(n + GTM - 1) / GTM, 256, smem>>>(x, W1, n);

    if (s2) {
        cudaEventRecord(evB, s2);
        cudaStreamWaitEvent(0, evB, 0);
    }

    k_layer1<<<(n + 15) / 16, 512>>>(b1, W2, n);
    long long thr = (long long)n * 32;
    k_agg2<<<(unsigned)((thr + 255) / 256), 256>>>(out, b2, n);
}

// round 17
// speedup vs baseline: 1.0111x; 1.0087x over previous
#include <cuda_runtime.h>
#include <cuda_fp16.h>
#include <cstdint>

#define NMAX   100000
#define EMAX   1600000
#define DIN    128
#define DH     128
#define DOUT   16

// ---------------- device scratch --------------------------------------------
__device__ __align__(16) float g_deg[NMAX];                 // dinv = rsqrt(deg+1)
__device__ __align__(16) uint2 g_h1h[(size_t)NMAX * 32];    // x @ W1 (half2 pairs)
__device__ __align__(16) float g_h2[(size_t)NMAX * DOUT];   // relu(...) @ W2 fp32
__device__ __align__(16) uint4 g_h2hx[(size_t)NMAX * 2];    // fp16(h2 * dinv), 16/row
__device__ int g_csr[EMAX];                                 // src indices by dst
__device__ int g_cnt[NMAX];   // zero at load; k_agg2 re-zeroes each call
__device__ int g_row[NMAX];
__device__ int g_cur[NMAX];
__device__ int g_excl[NMAX];
__device__ int g_bsum[128];

// ---------------- helpers ---------------------------------------------------
__device__ __forceinline__ void ffma2(unsigned long long& d,
                                      unsigned long long a, unsigned long long b) {
    asm("fma.rn.f32x2 %0, %1, %2, %0;" : "+l"(d) : "l"(a), "l"(b));
}
__device__ __forceinline__ unsigned long long pack2(float lo, float hi) {
    unsigned long long r;
    asm("mov.b64 %0, {%1, %2};" : "=l"(r) : "f"(lo), "f"(hi));
    return r;
}
__device__ __forceinline__ float2 unpack2(unsigned long long v) {
    float lo, hi;
    asm("mov.b64 {%0, %1}, %2;" : "=f"(lo), "=f"(hi) : "l"(v));
    return make_float2(lo, hi);
}
__device__ __forceinline__ float2 h2f2(uint32_t u) {
    return __half22float2(*reinterpret_cast<__half2*>(&u));
}
// per-block edge-index dtype detect (see R16 notes): warp 0 ballots high words
// of the first 32 qwords; misdetect prob ~(1e-5)^32.
#define DETECT_IS64(ei, s64)                                                 \
    do {                                                                     \
        if (threadIdx.x < 32) {                                              \
            const unsigned long long* _p = (const unsigned long long*)(ei);  \
            unsigned long long _v = _p[threadIdx.x];                         \
            unsigned _m = __ballot_sync(0xffffffffu, (_v >> 32) != 0ull);    \
            if (threadIdx.x == 0) (s64) = (_m == 0u);                        \
        }                                                                    \
        __syncthreads();                                                     \
    } while (0)

// ---------------- CSR construction ------------------------------------------
__global__ void k_count(const void* __restrict__ ei, int e) {
    __shared__ int s64;
    DETECT_IS64(ei, s64);
    int is64 = s64;
    int i = blockIdx.x * blockDim.x + threadIdx.x;
    if (i < e) {
        int d = is64 ? (int)__ldg(((const long long*)ei) + e + i)
                     : __ldg(((const int*)ei) + e + i);
        atomicAdd(&g_cnt[d], 1);
    }
}

__global__ void k_scan1(int n) {
    __shared__ int sh[256];
    int t = threadIdx.x;
    int base = blockIdx.x * 1024;
    int v[4], s = 0;
#pragma unroll
    for (int i = 0; i < 4; i++) {
        int idx = base + t * 4 + i;
        v[i] = (idx < n) ? g_cnt[idx] : 0;
        s += v[i];
    }
    sh[t] = s;
    __syncthreads();
    int own = s;
    for (int off = 1; off < 256; off <<= 1) {
        int o = (t >= off) ? sh[t - off] : 0;
        __syncthreads();
        sh[t] += o;
        __syncthreads();
    }
    if (t == 255) g_bsum[blockIdx.x] = sh[255];
    int run = sh[t] - own;
#pragma unroll
    for (int i = 0; i < 4; i++) {
        int idx = base + t * 4 + i;
        if (idx < n) g_excl[idx] = run;
        run += v[i];
    }
}

// scan3 (merged scan2): block b reduces bsum[0..b-1] -> prefix, finalizes.
__global__ void k_scan3(int n) {
    __shared__ int s_pre;
    int t = threadIdx.x;
    int b = blockIdx.x;
    if (t < 32) {
        int s = 0;
        for (int j = t; j < b; j += 32) s += g_bsum[j];
#pragma unroll
        for (int m = 16; m >= 1; m >>= 1) s += __shfl_xor_sync(0xffffffffu, s, m);
        if (t == 0) s_pre = s;
    }
    __syncthreads();
    int pre = s_pre;
#pragma unroll
    for (int q = 0; q < 4; q++) {
        int i = b * 1024 + q * 256 + t;
        if (i < n) {
            int r = g_excl[i] + pre;
            g_row[i] = r;
            g_cur[i] = r;
            g_deg[i] = rsqrtf((float)g_cnt[i] + 1.0f);
        }
    }
}

__global__ void k_fill(const void* __restrict__ ei, int e) {
    __shared__ int s64;
    DETECT_IS64(ei, s64);
    int is64 = s64;
    int i = blockIdx.x * blockDim.x + threadIdx.x;
    if (i < e) {
        int s, d;
        if (is64) {
            s = (int)__ldg(((const long long*)ei) + i);
            d = (int)__ldg(((const long long*)ei) + e + i);
        } else {
            s = __ldg(((const int*)ei) + i);
            d = __ldg(((const int*)ei) + e + i);
        }
        int pos = atomicAdd(&g_cur[d], 1);
        g_csr[pos] = s;
    }
}

// ---------------- GEMM1: h1h = fp16(x @ W1)  (FFMA2, transposed X tile) -----
#define GTM 64
#define XTS 66
__global__ void k_gemm1(const float* __restrict__ x,
                        const float* __restrict__ W1, int n) {
    extern __shared__ float sm[];
    float* Ws = sm;                 // 128*128
    float* Xt = sm + DIN * DH;      // [DIN][XTS]
    int t = threadIdx.x;

    for (int i = t; i < DIN * DH / 4; i += 256)
        reinterpret_cast<float4*>(Ws)[i] = reinterpret_cast<const float4*>(W1)[i];

    int row0 = blockIdx.x * GTM;
    for (int i = t; i < GTM * 32; i += 256) {
        int r = i >> 5, c4 = i & 31;
        int gr = row0 + r;
        float4 v = make_float4(0.f, 0.f, 0.f, 0.f);
        if (gr < n) v = reinterpret_cast<const float4*>(x)[(size_t)gr * 32 + c4];
        Xt[(c4 * 4 + 0) * XTS + r] = v.x;
        Xt[(c4 * 4 + 1) * XTS + r] = v.y;
        Xt[(c4 * 4 + 2) * XTS + r] = v.z;
        Xt[(c4 * 4 + 3) * XTS + r] = v.w;
    }
    __syncthreads();

    int cx = t & 31;
    int ry = t >> 5;
    unsigned long long acc[4][4];
#pragma unroll
    for (int p = 0; p < 4; p++)
#pragma unroll
        for (int c = 0; c < 4; c++) acc[p][c] = 0ull;

#pragma unroll 4
    for (int k = 0; k < DIN; k++) {
        float4 w = reinterpret_cast<const float4*>(Ws)[k * 32 + cx];
        unsigned long long ws[4];
        ws[0] = pack2(w.x, w.x); ws[1] = pack2(w.y, w.y);
        ws[2] = pack2(w.z, w.z); ws[3] = pack2(w.w, w.w);
        const unsigned long long* arow =
            reinterpret_cast<const unsigned long long*>(&Xt[k * XTS + ry * 8]);
#pragma unroll
        for (int p = 0; p < 4; p++) {
            unsigned long long ap = arow[p];
            ffma2(acc[p][0], ap, ws[0]);
            ffma2(acc[p][1], ap, ws[1]);
            ffma2(acc[p][2], ap, ws[2]);
            ffma2(acc[p][3], ap, ws[3]);
        }
    }
#pragma unroll
    for (int p = 0; p < 4; p++) {
        int gr = row0 + ry * 8 + 2 * p;
        float2 c0 = unpack2(acc[p][0]);
        float2 c1 = unpack2(acc[p][1]);
        float2 c2 = unpack2(acc[p][2]);
        float2 c3 = unpack2(acc[p][3]);
        if (gr < n) {
            __half2 h0 = __floats2half2_rn(c0.x, c1.x);
            __half2 h1 = __floats2half2_rn(c2.x, c3.x);
            uint2 u;
            u.x = *reinterpret_cast<uint32_t*>(&h0);
            u.y = *reinterpret_cast<uint32_t*>(&h1);
            g_h1h[(size_t)gr * 32 + cx] = u;
        }
        if (gr + 1 < n) {
            __half2 h0 = __floats2half2_rn(c0.y, c1.y);
            __half2 h1 = __floats2half2_rn(c2.y, c3.y);
            uint2 u;
            u.x = *reinterpret_cast<uint32_t*>(&h0);
            u.y = *reinterpret_cast<uint32_t*>(&h1);
            g_h1h[(size_t)(gr + 1) * 32 + cx] = u;
        }
    }
}

// ---------------- fused layer 1: gather + relu + GEMM2 ----------------------
// Emits g_h2 (fp32, unscaled) and g_h2hx = fp16(h2 * dinv[node]) so that
// k_agg2's per-edge messages need no weight load at all.
__global__ void __launch_bounds__(512) k_layer1(const float* __restrict__ b1,
                                                const float* __restrict__ W2, int n) {
    __shared__ float W2s[DH * DOUT];
    __shared__ float b1s[DH];
    __shared__ float vbuf[16 * 132];
    __shared__ float pbuf[256];
    int t = threadIdx.x;
    for (int i = t; i < DH * DOUT; i += 512) W2s[i] = W2[i];
    if (t < DH) b1s[t] = b1[t];
    __syncthreads();

    int warp = t >> 5, lane = t & 31;
    int node = blockIdx.x * 16 + warp;
    if (node < n) {
        int beg = g_row[node];
        int end = beg + g_cnt[node];
        float4 acc = make_float4(0.f, 0.f, 0.f, 0.f);
        int p = beg;
        for (; p + 3 < end; p += 4) {
            int s0 = __ldg(&g_csr[p]),     s1 = __ldg(&g_csr[p + 1]);
            int s2 = __ldg(&g_csr[p + 2]), s3 = __ldg(&g_csr[p + 3]);
            float w0 = g_deg[s0], w1 = g_deg[s1], w2 = g_deg[s2], w3 = g_deg[s3];
            uint2 u0 = g_h1h[(size_t)s0 * 32 + lane];
            uint2 u1 = g_h1h[(size_t)s1 * 32 + lane];
            uint2 u2 = g_h1h[(size_t)s2 * 32 + lane];
            uint2 u3 = g_h1h[(size_t)s3 * 32 + lane];
            float2 a0 = h2f2(u0.x), b0 = h2f2(u0.y);
            float2 a1 = h2f2(u1.x), b1v = h2f2(u1.y);
            float2 a2 = h2f2(u2.x), b2v = h2f2(u2.y);
            float2 a3 = h2f2(u3.x), b3v = h2f2(u3.y);
            acc.x += a0.x * w0 + a1.x * w1 + a2.x * w2 + a3.x * w3;
            acc.y += a0.y * w0 + a1.y * w1 + a2.y * w2 + a3.y * w3;
            acc.z += b0.x * w0 + b1v.x * w1 + b2v.x * w2 + b3v.x * w3;
            acc.w += b0.y * w0 + b1v.y * w1 + b2v.y * w2 + b3v.y * w3;
        }
        for (; p < end; p++) {
            int s0 = __ldg(&g_csr[p]);
            float w0 = g_deg[s0];
            uint2 u0 = g_h1h[(size_t)s0 * 32 + lane];
            float2 a0 = h2f2(u0.x), b0 = h2f2(u0.y);
            acc.x = fmaf(a0.x, w0, acc.x);
            acc.y = fmaf(a0.y, w0, acc.y);
            acc.z = fmaf(b0.x, w0, acc.z);
            acc.w = fmaf(b0.y, w0, acc.w);
        }
        float di = g_deg[node];
        float dd = di * di;
        uint2 us = g_h1h[(size_t)node * 32 + lane];
        float2 s0 = h2f2(us.x), s1 = h2f2(us.y);
        float4 bb = *reinterpret_cast<const float4*>(&b1s[lane * 4]);
        float4 v;
        v.x = fmaxf(fmaf(acc.x, di, fmaf(s0.x, dd, bb.x)), 0.f);
        v.y = fmaxf(fmaf(acc.y, di, fmaf(s0.y, dd, bb.y)), 0.f);
        v.z = fmaxf(fmaf(acc.z, di, fmaf(s1.x, dd, bb.z)), 0.f);
        v.w = fmaxf(fmaf(acc.w, di, fmaf(s1.y, dd, bb.w)), 0.f);
        *reinterpret_cast<float4*>(&vbuf[warp * 132 + lane * 4]) = v;
    }
    __syncthreads();

    // Phase 2: t<256 -> k 0..63; t>=256 -> k 64..127; combine via pbuf.
    {
        int tt = t & 255;
        int nl = tt >> 4;
        int j = tt & 15;
        int node2 = blockIdx.x * 16 + nl;
        int k0 = (t >= 256) ? 64 : 0;
        float acc = 0.f;
        if (node2 < n) {
            const float* vr = &vbuf[nl * 132 + k0];
            const float* wr = &W2s[k0 * DOUT + j];
#pragma unroll 8
            for (int k = 0; k < 64; k++)
                acc = fmaf(vr[k], wr[k * DOUT], acc);
        }
        if (t >= 256) pbuf[tt] = acc;
        __syncthreads();
        if (t < 256 && node2 < n) {
            acc += pbuf[tt];
            g_h2[(size_t)node2 * DOUT + j] = acc;
            // fp16 copy pre-scaled by dinv[node2] (removes agg2's deg gathers)
            float accs = acc * g_deg[node2];
            float nb = __shfl_xor_sync(0xffffffffu, accs, 1);
            if ((j & 1) == 0) {
                __half2 hp = __floats2half2_rn(accs, nb);
                ((uint32_t*)g_h2hx)[(size_t)node2 * 8 + (j >> 1)] =
                    *reinterpret_cast<uint32_t*>(&hp);
            }
        }
    }
}

// ---------------- layer-2 aggregation (pre-scaled fp16) + cnt restore -------
// out[d] = b2 + dd*h2[d] + di * Σ_s h2hx[s]   (h2hx already carries dinv[s])
__global__ void k_agg2(float* __restrict__ out, const float* __restrict__ b2, int n) {
    long long tid = (long long)blockIdx.x * blockDim.x + threadIdx.x;
    int node = (int)(tid >> 5);
    int lane = threadIdx.x & 31;
    if (node >= n) return;
    int eg = lane >> 1;
    int ch = lane & 1;
    int beg = g_row[node];
    int end = beg + g_cnt[node];
    float4 acc = make_float4(0.f, 0.f, 0.f, 0.f);
    float4 acc2 = make_float4(0.f, 0.f, 0.f, 0.f);
    for (int p0 = beg; p0 < end; p0 += 16) {
        int p = p0 + eg;
        if (p < end) {
            int s = __ldg(&g_csr[p]);
            uint4 u = g_h2hx[(size_t)s * 2 + ch];
            float2 f0 = h2f2(u.x), f1 = h2f2(u.y), f2 = h2f2(u.z), f3 = h2f2(u.w);
            acc.x  += f0.x;
            acc.y  += f0.y;
            acc.z  += f1.x;
            acc.w  += f1.y;
            acc2.x += f2.x;
            acc2.y += f2.y;
            acc2.z += f3.x;
            acc2.w += f3.y;
        }
    }
#pragma unroll
    for (int m = 2; m <= 16; m <<= 1) {
        acc.x  += __shfl_xor_sync(0xffffffffu, acc.x,  m);
        acc.y  += __shfl_xor_sync(0xffffffffu, acc.y,  m);
        acc.z  += __shfl_xor_sync(0xffffffffu, acc.z,  m);
        acc.w  += __shfl_xor_sync(0xffffffffu, acc.w,  m);
        acc2.x += __shfl_xor_sync(0xffffffffu, acc2.x, m);
        acc2.y += __shfl_xor_sync(0xffffffffu, acc2.y, m);
        acc2.z += __shfl_xor_sync(0xffffffffu, acc2.z, m);
        acc2.w += __shfl_xor_sync(0xffffffffu, acc2.w, m);
    }
    if (lane < 2) {
        float di = g_deg[node];
        float dd = di * di;
        int c0 = lane * 2;
        float4 bb0 = reinterpret_cast<const float4*>(b2)[c0];
        float4 bb1 = reinterpret_cast<const float4*>(b2)[c0 + 1];
        float4 hv0 = reinterpret_cast<const float4*>(g_h2)[(size_t)node * 4 + c0];
        float4 hv1 = reinterpret_cast<const float4*>(g_h2)[(size_t)node * 4 + c0 + 1];
        float4 o0, o1;
        o0.x = bb0.x + fmaf(hv0.x, dd, acc.x  * di);
        o0.y = bb0.y + fmaf(hv0.y, dd, acc.y  * di);
        o0.z = bb0.z + fmaf(hv0.z, dd, acc.z  * di);
        o0.w = bb0.w + fmaf(hv0.w, dd, acc.w  * di);
        o1.x = bb1.x + fmaf(hv1.x, dd, acc2.x * di);
        o1.y = bb1.y + fmaf(hv1.y, dd, acc2.y * di);
        o1.z = bb1.z + fmaf(hv1.z, dd, acc2.z * di);
        o1.w = bb1.w + fmaf(hv1.w, dd, acc2.w * di);
        reinterpret_cast<float4*>(out)[(size_t)node * 4 + c0]     = o0;
        reinterpret_cast<float4*>(out)[(size_t)node * 4 + c0 + 1] = o1;
    }
    // restore g_cnt to zero for the next call (deterministic invariant)
    if (lane == 0) g_cnt[node] = 0;
}

// ---------------- launch -----------------------------------------------------
extern "C" void kernel_launch(void* const* d_in, const int* in_sizes, int n_in,
                              void* d_out, int out_size) {
    const float* x  = (const float*)d_in[0];
    const void*  ei = d_in[1];
    const float* W1 = (const float*)d_in[2];
    const float* b1 = (const float*)d_in[3];
    const float* W2 = (const float*)d_in[4];
    const float* b2 = (const float*)d_in[5];
    float* out = (float*)d_out;

    int n = in_sizes[0] / DIN;
    int e = in_sizes[1] / 2;

    static cudaStream_t s2 = 0;
    static cudaEvent_t evA = 0, evB = 0;
    static int tried = 0;
    if (!tried) {
        tried = 1;
        if (cudaStreamCreateWithFlags(&s2, cudaStreamNonBlocking) != cudaSuccess) s2 = 0;
        if (s2) {
            if (cudaEventCreateWithFlags(&evA, cudaEventDisableTiming) != cudaSuccess ||
                cudaEventCreateWithFlags(&evB, cudaEventDisableTiming) != cudaSuccess) {
                s2 = 0;
            }
        }
    }
    cudaStream_t sc = s2 ? s2 : 0;

    if (s2) {
        cudaEventRecord(evA, 0);
        cudaStreamWaitEvent(s2, evA, 0);
    }

    // CSR build (side stream) — g_cnt arrives zeroed (BSS init / k_agg2 restore)
    k_count<<<(e + 255) / 256, 256, 0, sc>>>(ei, e);
    int nb = (n + 1023) / 1024;
    k_scan1<<<nb, 256, 0, sc>>>(n);
    k_scan3<<<nb, 256, 0, sc>>>(n);
    k_fill<<<(e + 255) / 256, 256, 0, sc>>>(ei, e);

    // GEMM1 (default stream, concurrent with CSR build)
    int smem = (DIN * DH + DIN * XTS) * (int)sizeof(float);   // ~97 KB
    cudaFuncSetAttribute(k_gemm1, cudaFuncAttributeMaxDynamicSharedMemorySize, smem);
    k_gemm1<<<(n + GTM - 1) / GTM, 256, smem>>>(x, W1, n);

    if (s2) {
        cudaEventRecord(evB, s2);
        cudaStreamWaitEvent(0, evB, 0);
    }

    k_layer1<<<(n + 15) / 16, 512>>>(b1, W2, n);
    long long thr = (long long)n * 32;
    k_agg2<<<(unsigned)((thr + 255) / 256), 256>>>(out, b2, n);
}